// round 11
// baseline (speedup 1.0000x reference)
#include <cuda_runtime.h>
#include <cuda_fp16.h>
#include <mma.h>
#include <cstdint>

using namespace nvcuda;

#define BATCH 64
#define TT    256
#define HHH   1024
#define GGG   4096
#define MTOT  (BATCH*TT)   // 16384

#define NBLK  128
#define NTHR  256
#define WLD   1032         // weight smem row stride (half elems), mult of 8
#define CHUNK 512
#define ALD   520          // A-tile smem row stride (half elems), mult of 8
#define ABUF  (64*ALD)     // halfs per A buffer

// Dynamic smem: 32*WLD*2 + 2*ABUF*2 + 64*36*4 + 32*4
#define SMEM_TOTAL (66048 + 133120 + 9216 + 128)

// ----------------------------------------------------------------------------
// Device-global scratch (allocation-free)
// ----------------------------------------------------------------------------
__device__ __align__(16) half  g_wih[3][GGG*HHH];
__device__ __align__(16) half  g_whh[3][GGG*HHH];
__device__            float g_bias[3][GGG];
__device__ __align__(16) float g_xg[(size_t)MTOT*GGG];    // 268 MB; permuted gate cols
__device__ __align__(16) half  g_in[(size_t)MTOT*HHH];    // layer input (layers 1,2)
__device__ __align__(16) half  g_h[2][BATCH*HHH];         // double-buffered hidden
__device__            float g_hlast[BATCH*HHH];           // final h of last layer (fp32)
__device__            unsigned g_bar;                     // grid barrier counter

// Gate-row permutation: permuted row cp -> original row of [4H, K] weight.
__device__ __forceinline__ int perm_row(int cp) {
    int nb = cp >> 5, r = cp & 31;
    return (r >> 3) * HHH + nb * 8 + (r & 7);
}

__device__ __forceinline__ float fsig(float x) {
    return 1.f / (1.f + __expf(-x));
}
__device__ __forceinline__ float ftanh(float x) {
    return 1.f - 2.f / (__expf(2.f * x) + 1.f);
}

// ----------------------------------------------------------------------------
// Prep kernels
// ----------------------------------------------------------------------------
__global__ void prep_w_kernel(const float* __restrict__ w, int l, int which, int cols) {
    size_t idx = (size_t)blockIdx.x * blockDim.x + threadIdx.x;
    size_t n = (size_t)GGG * cols;
    if (idx >= n) return;
    int rp = (int)(idx / cols), c = (int)(idx % cols);
    int r = perm_row(rp);
    float v = w[(size_t)r * cols + c];
    if (which == 0) g_wih[l][idx] = __float2half(v);
    else            g_whh[l][idx] = __float2half(v);
}

__global__ void prep_bias_kernel(const float* __restrict__ bih,
                                 const float* __restrict__ bhh, int l) {
    int cp = blockIdx.x * blockDim.x + threadIdx.x;
    if (cp < GGG) { int r = perm_row(cp); g_bias[l][cp] = bih[r] + bhh[r]; }
}

__global__ void init_state_kernel() {
    int i = blockIdx.x * blockDim.x + threadIdx.x;  // 65536 total
    g_h[0][i] = __float2half(0.f);
    if (i == 0) g_bar = 0u;
}

// ----------------------------------------------------------------------------
// xg GEMM: g_xg[M,4096] = A[M,K](fp16) @ B[4096,K]^T(fp16), fp32 accum.
// Block tile 128x128, 8 warps (2x4), warp tile 64x32, k-chunk 32.
// Register-staged double-buffered pipeline (LDG next | MMA cur | STS next).
// For layer 0, A is read directly from fp32 x and converted on the fly.
// ----------------------------------------------------------------------------
__global__ void __launch_bounds__(256) xg_gemm_kernel(int l, int K,
                                                      const float* __restrict__ xsrc) {
    __shared__ __align__(32) half sA[2][128][40], sB[2][128][40];
    int m0 = blockIdx.y * 128, n0 = blockIdx.x * 128;
    int tid = threadIdx.x, warp = tid >> 5;
    int wm = warp >> 2, wn = warp & 3;
    bool f32src = (l == 0);

    wmma::fragment<wmma::accumulator, 16, 16, 16, float> acc[4][2];
#pragma unroll
    for (int i = 0; i < 4; i++)
#pragma unroll
        for (int j = 0; j < 2; j++) wmma::fill_fragment(acc[i][j], 0.f);

    const half* B = g_wih[l];
    int r = tid >> 1, c16 = (tid & 1) * 16;

    uint4 ra[2], rb[2];

    // --- load helpers (macros to keep regs in scope) ---
#define LOAD_A(k0)                                                             \
    do {                                                                       \
        if (f32src) {                                                          \
            const float* p = xsrc + (size_t)(m0 + r) * K + (k0) + c16;         \
            float4 f0 = *(const float4*)(p + 0);                               \
            float4 f1 = *(const float4*)(p + 4);                               \
            float4 f2 = *(const float4*)(p + 8);                               \
            float4 f3 = *(const float4*)(p + 12);                              \
            __half2 h0 = __floats2half2_rn(f0.x, f0.y);                        \
            __half2 h1 = __floats2half2_rn(f0.z, f0.w);                        \
            __half2 h2 = __floats2half2_rn(f1.x, f1.y);                        \
            __half2 h3 = __floats2half2_rn(f1.z, f1.w);                        \
            __half2 h4 = __floats2half2_rn(f2.x, f2.y);                        \
            __half2 h5 = __floats2half2_rn(f2.z, f2.w);                        \
            __half2 h6 = __floats2half2_rn(f3.x, f3.y);                        \
            __half2 h7 = __floats2half2_rn(f3.z, f3.w);                        \
            ra[0] = make_uint4(*(unsigned*)&h0, *(unsigned*)&h1,               \
                               *(unsigned*)&h2, *(unsigned*)&h3);              \
            ra[1] = make_uint4(*(unsigned*)&h4, *(unsigned*)&h5,               \
                               *(unsigned*)&h6, *(unsigned*)&h7);              \
        } else {                                                               \
            const half* p = g_in + (size_t)(m0 + r) * K + (k0) + c16;          \
            ra[0] = *(const uint4*)p;                                          \
            ra[1] = *(const uint4*)(p + 8);                                    \
        }                                                                      \
    } while (0)

#define LOAD_B(k0)                                                             \
    do {                                                                       \
        const half* p = B + (size_t)(n0 + r) * K + (k0) + c16;                 \
        rb[0] = *(const uint4*)p;                                              \
        rb[1] = *(const uint4*)(p + 8);                                        \
    } while (0)

#define STS(buf)                                                               \
    do {                                                                       \
        *(uint4*)&sA[buf][r][c16]     = ra[0];                                 \
        *(uint4*)&sA[buf][r][c16 + 8] = ra[1];                                 \
        *(uint4*)&sB[buf][r][c16]     = rb[0];                                 \
        *(uint4*)&sB[buf][r][c16 + 8] = rb[1];                                 \
    } while (0)

    int nch = K / 32;
    LOAD_A(0); LOAD_B(0);
    STS(0);
    __syncthreads();

    for (int ch = 0; ch < nch; ch++) {
        int cur = ch & 1;
        if (ch + 1 < nch) { LOAD_A((ch + 1) * 32); LOAD_B((ch + 1) * 32); }

#pragma unroll
        for (int ks = 0; ks < 2; ks++) {
            wmma::fragment<wmma::matrix_a, 16, 16, 16, half, wmma::row_major> af[4];
            wmma::fragment<wmma::matrix_b, 16, 16, 16, half, wmma::col_major> bf[2];
#pragma unroll
            for (int i = 0; i < 4; i++)
                wmma::load_matrix_sync(af[i], &sA[cur][wm * 64 + i * 16][ks * 16], 40);
#pragma unroll
            for (int j = 0; j < 2; j++)
                wmma::load_matrix_sync(bf[j], &sB[cur][wn * 32 + j * 16][ks * 16], 40);
#pragma unroll
            for (int i = 0; i < 4; i++)
#pragma unroll
                for (int j = 0; j < 2; j++)
                    wmma::mma_sync(acc[i][j], af[i], bf[j], acc[i][j]);
        }
        if (ch + 1 < nch) STS(cur ^ 1);
        __syncthreads();
    }
#undef LOAD_A
#undef LOAD_B
#undef STS

#pragma unroll
    for (int i = 0; i < 4; i++)
#pragma unroll
        for (int j = 0; j < 2; j++) {
            size_t row = (size_t)(m0 + wm * 64 + i * 16);
            int col = n0 + wn * 32 + j * 16;
            wmma::store_matrix_sync(&g_xg[row * GGG + col], acc[i][j], GGG,
                                    wmma::mem_row_major);
        }
}

// ----------------------------------------------------------------------------
// Persistent recurrence kernel: one launch per LAYER (grid=128, co-resident).
// Block nb owns permuted gate rows [32nb,32nb+32) => h slice [8nb, 8nb+8).
// Whh slice (fp16, 64KB) in smem for all 256 steps; c in registers.
// Dual accumulators (even/odd k-step) halve the MMA dependency chain.
// ----------------------------------------------------------------------------
__global__ void __launch_bounds__(NTHR, 1) layer_kernel(int l) {
    extern __shared__ __align__(16) char smem_raw[];
    half*  sW    = (half*)smem_raw;               // [32][WLD]
    half*  sA    = sW + 32 * WLD;                 // [2 bufs][64][ALD]
    float* sg    = (float*)(sA + 2 * ABUF);       // [64][36]
    float* sbias = sg + 64 * 36;                  // [32]

    int nb = blockIdx.x;
    int tid = threadIdx.x, warp = tid >> 5;
    int wm = warp >> 1, wn = warp & 1;            // 4x2 warps over 64x32 tile

    // --- Load Whh slice into smem (once per layer) ---
    {
        const half* Bw = &g_whh[l][(size_t)(nb * 32) * HHH];
        for (int i = tid; i < 32 * 128; i += NTHR) {
            int r = i >> 7, c = (i & 127) * 8;
            *(uint4*)&sW[r * WLD + c] = *(const uint4*)&Bw[(size_t)r * HHH + c];
        }
        if (tid < 32) sbias[tid] = g_bias[l][nb * 32 + tid];
    }
    __syncthreads();

    int bq = tid >> 2;
    int hh2 = (tid & 3) * 2;
    float c0 = 0.f, c1 = 0.f;

    wmma::fragment<wmma::accumulator, 16, 16, 16, float> acc0, acc1;

    for (int t = 0; t < TT; t++) {
        int rp = t & 1, wp = rp ^ 1;
        const half* Ah = g_h[rp];

        // Prefetch xg tile values (latency hidden by k-loop)
        size_t xbase = ((size_t)bq * TT + t) * GGG + nb * 32;
        float2 x0 = *(const float2*)&g_xg[xbase + hh2];
        float2 x1 = *(const float2*)&g_xg[xbase + 8 + hh2];
        float2 x2 = *(const float2*)&g_xg[xbase + 16 + hh2];
        float2 x3 = *(const float2*)&g_xg[xbase + 24 + hh2];

        wmma::fill_fragment(acc0, 0.f);
        wmma::fill_fragment(acc1, 0.f);

        // Prologue: chunk 0 -> buf 0  (64 rows x 512 halfs = 4096 uint4)
#pragma unroll
        for (int u = 0; u < 16; u++) {
            int idx = tid + u * NTHR;
            int r = idx >> 6, c = (idx & 63) * 8;
            *(uint4*)&sA[0 * ABUF + r * ALD + c] = *(const uint4*)&Ah[(size_t)r * HHH + c];
        }
        __syncthreads();

#pragma unroll
        for (int ch = 0; ch < 2; ch++) {
            if (ch == 0) {
                // prefetch chunk 1 -> buf 1 (overlaps with chunk-0 MMAs)
#pragma unroll
                for (int u = 0; u < 16; u++) {
                    int idx = tid + u * NTHR;
                    int r = idx >> 6, c = (idx & 63) * 8;
                    *(uint4*)&sA[1 * ABUF + r * ALD + c] =
                        *(const uint4*)&Ah[(size_t)r * HHH + CHUNK + c];
                }
            }
            const half* bufA = sA + ch * ABUF;
#pragma unroll
            for (int ks = 0; ks < 32; ks++) {
                wmma::fragment<wmma::matrix_a, 16, 16, 16, half, wmma::row_major> af;
                wmma::fragment<wmma::matrix_b, 16, 16, 16, half, wmma::col_major> bf;
                wmma::load_matrix_sync(af, &bufA[(wm * 16) * ALD + ks * 16], ALD);
                wmma::load_matrix_sync(bf, &sW[(wn * 16) * WLD + ch * CHUNK + ks * 16], WLD);
                if (ks & 1) wmma::mma_sync(acc1, af, bf, acc1);
                else        wmma::mma_sync(acc0, af, bf, acc0);
            }
            if (ch == 0) __syncthreads();   // buf1 ready before chunk-1 MMAs
        }

        // Merge accumulators and stage gates to smem
#pragma unroll
        for (int i = 0; i < acc0.num_elements; i++) acc0.x[i] += acc1.x[i];
        wmma::store_matrix_sync(&sg[(wm * 16) * 36 + wn * 16], acc0, 36, wmma::mem_row_major);
        __syncthreads();   // also protects A-buffer reuse next step

        // Fused LSTM cell update (2 (b,hh) pairs per thread)
        {
            float iv0 = sg[bq * 36 + hh2]          + x0.x + sbias[hh2];
            float iv1 = sg[bq * 36 + hh2 + 1]      + x0.y + sbias[hh2 + 1];
            float fv0 = sg[bq * 36 + 8 + hh2]      + x1.x + sbias[8 + hh2];
            float fv1 = sg[bq * 36 + 8 + hh2 + 1]  + x1.y + sbias[8 + hh2 + 1];
            float gv0 = sg[bq * 36 + 16 + hh2]     + x2.x + sbias[16 + hh2];
            float gv1 = sg[bq * 36 + 16 + hh2 + 1] + x2.y + sbias[16 + hh2 + 1];
            float ov0 = sg[bq * 36 + 24 + hh2]     + x3.x + sbias[24 + hh2];
            float ov1 = sg[bq * 36 + 24 + hh2 + 1] + x3.y + sbias[24 + hh2 + 1];

            c0 = fsig(fv0) * c0 + fsig(iv0) * ftanh(gv0);
            c1 = fsig(fv1) * c1 + fsig(iv1) * ftanh(gv1);
            float h0 = fsig(ov0) * ftanh(c0);
            float h1 = fsig(ov1) * ftanh(c1);

            int hidx = nb * 8 + hh2;
            __half2 ph;
            ph.x = __float2half(h0);
            ph.y = __float2half(h1);
            *(__half2*)&g_h[wp][bq * HHH + hidx] = ph;
            if (l < 2) {
                size_t m = (size_t)bq * TT + t;
                *(__half2*)&g_in[m * HHH + hidx] = ph;
            }
            if (l == 2 && t == TT - 1) {
                g_hlast[bq * HHH + hidx]     = h0;
                g_hlast[bq * HHH + hidx + 1] = h1;
            }
        }

        // Grid barrier (skip after last step)
        if (t < TT - 1) {
            __threadfence();
            __syncthreads();
            if (tid == 0) {
                atomicAdd(&g_bar, 1u);
                unsigned want = (unsigned)(t + 1) * NBLK;
                volatile unsigned* p = &g_bar;
                while (*p < want) { }
                __threadfence();
            }
            __syncthreads();
        }
    }
}

// ----------------------------------------------------------------------------
// Final FC: out[b] = hlast[b, :] . fc_w + fc_b   (D_OUT = 1)
// ----------------------------------------------------------------------------
__global__ void fc_kernel(const float* __restrict__ fw, const float* __restrict__ fb,
                          float* __restrict__ out) {
    int b = blockIdx.x, tid = threadIdx.x;
    __shared__ float red[256];
    const float* hrow = &g_hlast[b * HHH];
    float s = 0.f;
    for (int h = tid; h < HHH; h += 256) s += hrow[h] * fw[h];
    red[tid] = s;
    __syncthreads();
    for (int off = 128; off; off >>= 1) {
        if (tid < off) red[tid] += red[tid + off];
        __syncthreads();
    }
    if (tid == 0) out[b] = red[0] + fb[0];
}

// ----------------------------------------------------------------------------
// Launch (ordered so profile index 4/5 hits xg_gemm / layer_kernel)
// ----------------------------------------------------------------------------
extern "C" void kernel_launch(void* const* d_in, const int* in_sizes, int n_in,
                              void* d_out, int out_size) {
    const float* x = (const float*)d_in[0];

    cudaFuncSetAttribute(layer_kernel, cudaFuncAttributeMaxDynamicSharedMemorySize,
                         SMEM_TOTAL);

    for (int l = 0; l < 3; l++) {
        int K = (l == 0) ? 256 : 1024;
        size_t nih = (size_t)GGG * K;
        prep_w_kernel<<<(unsigned)((nih + 255) / 256), 256>>>(
            (const float*)d_in[1 + 4 * l], l, 0, K);
        prep_w_kernel<<<(GGG * HHH + 255) / 256, 256>>>(
            (const float*)d_in[2 + 4 * l], l, 1, HHH);
        prep_bias_kernel<<<16, 256>>>(
            (const float*)d_in[3 + 4 * l], (const float*)d_in[4 + 4 * l], l);
        init_state_kernel<<<256, 256>>>();
        dim3 grid(GGG / 128, MTOT / 128);
        xg_gemm_kernel<<<grid, 256>>>(l, K, x);
        layer_kernel<<<NBLK, NTHR, SMEM_TOTAL>>>(l);
    }
    fc_kernel<<<BATCH, 256>>>((const float*)d_in[13], (const float*)d_in[14],
                              (float*)d_out);
}